// round 5
// baseline (speedup 1.0000x reference)
#include <cuda_runtime.h>
#include <cuda_bf16.h>

// Problem dims (fixed by setup_inputs): pred (N,V,C,T,H,W) = (8,3,24,8,128,128)
#define N_ 8
#define V_ 3
#define C_ 24
#define T_ 8
#define H_ 128
#define W_ 128
#define HW_ (H_ * W_)                 // 16384
#define NSLICES (N_ * V_ * C_ * T_)   // 4608
#define NMASK (N_ * HW_)              // 131072
#define SLICES_PER_CTA 2
#define NCTAS (NSLICES / SLICES_PER_CTA)  // 2304

// Fixed scratch (no dynamic allocation allowed)
__device__ float g_partials[NCTAS];

__device__ __forceinline__ float warp_sum(float v) {
    #pragma unroll
    for (int off = 16; off > 0; off >>= 1)
        v += __shfl_xor_sync(0xFFFFFFFFu, v, off);
    return v;
}

__global__ __launch_bounds__(256) void slice_reduce_kernel(
    const float* __restrict__ pred,
    const int* __restrict__ mask,
    const float* __restrict__ vq,
    float* __restrict__ partials)
{
    float acc0 = 0.0f, acc1 = 0.0f;   // two chains: hide FFMA latency

    #pragma unroll
    for (int sub = 0; sub < SLICES_PER_CTA; sub++) {
        const int s = blockIdx.x * SLICES_PER_CTA + sub;  // slice over (n,v,c,t)
        const int n = s / (V_ * C_ * T_);
        const int c = (s / T_) % C_;

        const float4* __restrict__ p4 = reinterpret_cast<const float4*>(pred + (size_t)s * HW_);
        const int4*  __restrict__ m4 = reinterpret_cast<const int4*>(mask + (size_t)n * HW_);
        const float vqc = vq[c];

        // HW_/4 = 4096 float4 per slice; 256 threads -> 16 iters; process 2/iter
        #pragma unroll 2
        for (int i = threadIdx.x; i < HW_ / 4; i += 512) {
            float4 pa = p4[i];
            float4 pb = p4[i + 256];
            int4  ma = m4[i];
            int4  mb = m4[i + 256];
            acc0 = fmaf(fabsf(pa.x - vqc), (float)(1 - ma.x), acc0);
            acc1 = fmaf(fabsf(pa.y - vqc), (float)(1 - ma.y), acc1);
            acc0 = fmaf(fabsf(pa.z - vqc), (float)(1 - ma.z), acc0);
            acc1 = fmaf(fabsf(pa.w - vqc), (float)(1 - ma.w), acc1);
            acc0 = fmaf(fabsf(pb.x - vqc), (float)(1 - mb.x), acc0);
            acc1 = fmaf(fabsf(pb.y - vqc), (float)(1 - mb.y), acc1);
            acc0 = fmaf(fabsf(pb.z - vqc), (float)(1 - mb.z), acc0);
            acc1 = fmaf(fabsf(pb.w - vqc), (float)(1 - mb.w), acc1);
        }
    }

    float acc = acc0 + acc1;

    // warp-level then cross-warp reduction (8 warps)
    acc = warp_sum(acc);
    __shared__ float swarp[8];
    const int lane = threadIdx.x & 31;
    const int wid = threadIdx.x >> 5;
    if (lane == 0) swarp[wid] = acc;
    __syncthreads();
    if (wid == 0) {
        float v = (lane < 8) ? swarp[lane] : 0.0f;
        #pragma unroll
        for (int off = 4; off > 0; off >>= 1)
            v += __shfl_xor_sync(0xFFFFFFFFu, v, off);
        if (lane == 0) partials[blockIdx.x] = v;
    }
}

__global__ __launch_bounds__(1024) void final_reduce_kernel(
    const float* __restrict__ partials,
    const int* __restrict__ mask,
    float* __restrict__ out)
{
    const int tid = threadIdx.x;

    double num = 0.0;
    for (int i = tid; i < NCTAS; i += 1024) num += (double)partials[i];

    long long zeros = 0;
    const int4* __restrict__ m4 = reinterpret_cast<const int4*>(mask);
    for (int i = tid; i < NMASK / 4; i += 1024) {
        int4 m = m4[i];
        zeros += (long long)(4 - m.x - m.y - m.z - m.w);
    }

    __shared__ double snum[1024];
    __shared__ long long szero[1024];
    snum[tid] = num;
    szero[tid] = zeros;
    __syncthreads();
    #pragma unroll
    for (int off = 512; off > 0; off >>= 1) {
        if (tid < off) {
            snum[tid] += snum[tid + off];
            szero[tid] += szero[tid + off];
        }
        __syncthreads();
    }
    if (tid == 0) {
        double den = (double)szero[0] * (double)(V_ * C_ * T_);
        out[0] = (float)(snum[0] / den);
    }
}

extern "C" void kernel_launch(void* const* d_in, const int* in_sizes, int n_in,
                              void* d_out, int out_size)
{
    const float* pred = (const float*)d_in[0];
    const int*  mask = (const int*)d_in[1];
    const float* vq  = (const float*)d_in[2];
    float* out = (float*)d_out;

    float* partials_dev;
    cudaGetSymbolAddress((void**)&partials_dev, g_partials);

    slice_reduce_kernel<<<NCTAS, 256>>>(pred, mask, vq, partials_dev);
    final_reduce_kernel<<<1, 1024>>>(partials_dev, mask, out);
}